// round 11
// baseline (speedup 1.0000x reference)
#include <cuda_runtime.h>
#include <math.h>

// Shapes: feature (8,128,80,256) fp32; ln_weight/ln_bias (128)
// B2=4, H=80, W=256, C=128
// Outputs (concatenated fp32):
//   disparity (4,1,80,256)   @ 0          (81920)
//   conf      (4,1,80,256)   @ 81920      (81920)
//   occ       (4,1,80,256)   @ 163840     (81920)
//   cv        (4,80,256,256) @ 245760     (20971520)
//   cv_down   (4,40,128,128) @ 21217280   (2621440)

#define NEG_INF __int_as_float(0xff800000)

// 84 MB scratch: first holds xn, then reused as cvT.
__device__ float g_scratch[20971520];

// ---------------------------------------------------------------------------
// ~1-ulp fp32 exp/log from FFMA polynomials; deterministic, fast-math-immune.
// ---------------------------------------------------------------------------
__device__ __forceinline__ float exp_acc(float x) {
    if (x < -87.0f) return 0.f;
    float kf = rintf(x * 1.44269504088896341f);
    float f  = fmaf(kf, -6.93145752e-1f, x);
    f        = fmaf(kf, -1.42860677e-6f, f);
    float p = 1.98412698e-4f;
    p = fmaf(p, f, 1.38888889e-3f);
    p = fmaf(p, f, 8.33333333e-3f);
    p = fmaf(p, f, 4.16666667e-2f);
    p = fmaf(p, f, 1.66666667e-1f);
    p = fmaf(p, f, 5.0e-1f);
    p = fmaf(p, f, 1.0f);
    p = fmaf(p, f, 1.0f);
    int ki = (int)kf;
    return p * __int_as_float((ki + 127) << 23);
}

__device__ __forceinline__ float log_acc(float x) {
    int ix = __float_as_int(x);
    int e  = (ix >> 23) - 127;
    float mf = __int_as_float((ix & 0x7FFFFF) | 0x3F800000);
    if (mf > 1.41421356f) { mf *= 0.5f; e += 1; }
    float r  = (mf - 1.0f) / (mf + 1.0f);
    float r2 = r * r;
    float p = 0.10376f;
    p = fmaf(p, r2, 0.11119022f);
    p = fmaf(p, r2, 0.14285414f);
    p = fmaf(p, r2, 0.20000029f);
    p = fmaf(p, r2, 0.33333333f);
    p = fmaf(p, r2, 1.0f);
    p = 2.0f * r * p;
    float ef = (float)e;
    return fmaf(ef, 6.93145752e-1f, p) + ef * 1.42860677e-6f;
}

// ---------------------------------------------------------------------------
// Kernel 1: LayerNorm emulating XLA-CPU bit order (serial fp32 sums).
// feature[b,c,h,i] -> xn[((b*80+h)*256+i)*128+c]
// ---------------------------------------------------------------------------
__global__ void __launch_bounds__(256) ln_kernel(const float* __restrict__ f,
                                                 const float* __restrict__ lw,
                                                 const float* __restrict__ lb,
                                                 float* __restrict__ xn) {
    __shared__ float tile[128][65];
    __shared__ float mu[64], rs[64];
    __shared__ float wv[128], bv[128];
    int i0  = blockIdx.x * 64;
    int h   = blockIdx.y;
    int b   = blockIdx.z;
    int tid = threadIdx.x;
    if (tid < 128) { wv[tid] = lw[tid]; bv[tid] = lb[tid]; }

    const float* fp = f + ((b * 128) * 80 + h) * 256 + i0;
    for (int idx = tid; idx < 128 * 64; idx += 256) {
        int c = idx >> 6, ii = idx & 63;
        tile[c][ii] = fp[c * (80 * 256) + ii];
    }
    __syncthreads();

    if (tid < 64) {
        float s = 0.f;
        for (int c = 0; c < 128; ++c) s = __fadd_rn(s, tile[c][tid]);
        float muf = __fmul_rn(s, 0.0078125f);           // exact /128
        float vs = 0.f;
        for (int c = 0; c < 128; ++c) {
            float d = __fsub_rn(tile[c][tid], muf);
            vs = __fadd_rn(vs, __fmul_rn(d, d));
        }
        float varf = __fmul_rn(vs, 0.0078125f);
        mu[tid] = muf;
        rs[tid] = __fdiv_rn(1.0f, __fsqrt_rn(__fadd_rn(varf, 1e-5f)));
    }
    __syncthreads();

    float* op = xn + ((b * 80 + h) * 256 + i0) * 128;
    for (int idx = tid; idx < 8192; idx += 256) {
        int ii = idx >> 7, c = idx & 127;
        float xm = __fsub_rn(tile[c][ii], mu[ii]);
        float t  = __fmul_rn(__fmul_rn(xm, rs[ii]), wv[c]);
        op[ii * 128 + c] = __fadd_rn(t, bv[c]);
    }
}

// ---------------------------------------------------------------------------
// Kernel 2: cv = f0 @ f1^T per (b,h). Serial ascending-k FMA chain per output.
// Fused cv_down epilogue (even-h CTAs, bitwise-identical register values).
// ---------------------------------------------------------------------------
__global__ void __launch_bounds__(256) gemm_kernel(const float* __restrict__ xn,
                                                   float* __restrict__ cv,
                                                   float* __restrict__ cvd) {
    __shared__ float As[32][128];
    __shared__ float Bs[32][128];
    int bh = blockIdx.y;
    int ti = blockIdx.x >> 1, tj = blockIdx.x & 1;
    const float* Ag = xn + bh * 32768 + ti * 16384;
    const float* Bg = xn + (bh + 320) * 32768 + tj * 16384;
    int tid = threadIdx.x;
    int m0 = (tid >> 4) << 3;
    int n0 = (tid & 15) << 3;

    float acc[8][8];
    #pragma unroll
    for (int r = 0; r < 8; ++r)
        #pragma unroll
        for (int c = 0; c < 8; ++c) acc[r][c] = 0.f;

    for (int k0 = 0; k0 < 128; k0 += 32) {
        __syncthreads();
        #pragma unroll
        for (int q = tid; q < 1024; q += 256) {
            int m = q & 127, kq = q >> 7;
            float4 va = *(const float4*)(Ag + m * 128 + k0 + kq * 4);
            As[kq * 4 + 0][m] = va.x; As[kq * 4 + 1][m] = va.y;
            As[kq * 4 + 2][m] = va.z; As[kq * 4 + 3][m] = va.w;
            float4 vb = *(const float4*)(Bg + m * 128 + k0 + kq * 4);
            Bs[kq * 4 + 0][m] = vb.x; Bs[kq * 4 + 1][m] = vb.y;
            Bs[kq * 4 + 2][m] = vb.z; Bs[kq * 4 + 3][m] = vb.w;
        }
        __syncthreads();
        #pragma unroll 8
        for (int k = 0; k < 32; ++k) {
            float4 a0 = *(const float4*)&As[k][m0];
            float4 a1 = *(const float4*)&As[k][m0 + 4];
            float4 b0 = *(const float4*)&Bs[k][n0];
            float4 b1 = *(const float4*)&Bs[k][n0 + 4];
            float a[8] = {a0.x, a0.y, a0.z, a0.w, a1.x, a1.y, a1.z, a1.w};
            float bb[8] = {b0.x, b0.y, b0.z, b0.w, b1.x, b1.y, b1.z, b1.w};
            #pragma unroll
            for (int r = 0; r < 8; ++r)
                #pragma unroll
                for (int c = 0; c < 8; ++c) acc[r][c] = fmaf(a[r], bb[c], acc[r][c]);
        }
    }

    float* Cp = cv + bh * 65536 + (ti * 128 + m0) * 256 + tj * 128 + n0;
    #pragma unroll
    for (int r = 0; r < 8; ++r) {
        *(float4*)(Cp + r * 256)     = make_float4(acc[r][0], acc[r][1], acc[r][2], acc[r][3]);
        *(float4*)(Cp + r * 256 + 4) = make_float4(acc[r][4], acc[r][5], acc[r][6], acc[r][7]);
    }

    // Fused cv_down: cvd[b,hd,id,jd] = cv[b, 2hd, 2id, 2jd]
    int h = bh % 80;
    if (!(h & 1)) {
        int b  = bh / 80;
        int hd = h >> 1;
        float* Dp = cvd + ((b * 40 + hd) << 14);   // 128*128 per (b,hd)
        int jd0 = (tj * 128 + n0) >> 1;            // multiple of 4
        #pragma unroll
        for (int r = 0; r < 8; r += 2) {
            int id = (ti * 128 + m0 + r) >> 1;
            *(float4*)(Dp + id * 128 + jd0) =
                make_float4(acc[r][0], acc[r][2], acc[r][4], acc[r][6]);
        }
    }
}

// ---------------------------------------------------------------------------
// Kernel 3: per-(b,h) 256x256 transpose cv -> cvT
// ---------------------------------------------------------------------------
__global__ void __launch_bounds__(256) transpose_kernel(const float* __restrict__ cv,
                                                        float* __restrict__ cvT) {
    __shared__ float t[32][33];
    int bh = blockIdx.y;
    int ti = blockIdx.x >> 3, tj = blockIdx.x & 7;
    const float* src = cv + bh * 65536;
    float* dst = cvT + bh * 65536;
    int x = threadIdx.x & 31;
    int y = threadIdx.x >> 5;
    int i0 = ti * 32, j0 = tj * 32;
    #pragma unroll
    for (int r = y; r < 32; r += 8) t[r][x] = src[(i0 + r) * 256 + j0 + x];
    __syncthreads();
    #pragma unroll
    for (int r = y; r < 32; r += 8) dst[(j0 + r) * 256 + i0 + x] = t[x][r];
}

// ---------------------------------------------------------------------------
// Kernel 4: Sinkhorn + outputs. Bit-order identical to R6/R9 (XLA-CPU serial
// fp32 chains). New structure:
//   Phase A (16 warps, 2 lines each): lane owns j = lane+32k (k=0..7);
//     t kept in registers, warp-max via shfl, exp from registers, single STS
//     of p (zeros in masked positions -> x+0.0f is bitwise exact, so the
//     uniform 256-length chain matches the reference's serial order that
//     also adds exp(-inf)=0 at masked slots). Invalid chunks skipped.
//   Phase B (warp 0, thread-per-line): uniform 256-add serial fp32 chain
//     over conflict-free stride-261 pbuf; pad element added LAST.
// Static smem ~36 KB -> 4 CTAs/SM, all 320 CTAs in one wave.
// ---------------------------------------------------------------------------
__global__ void __launch_bounds__(512) sinkhorn_kernel(const float* __restrict__ cv,
                                                       const float* __restrict__ cvT,
                                                       float* __restrict__ disp,
                                                       float* __restrict__ conf,
                                                       float* __restrict__ occ) {
    __shared__ float u[260], v[260];
    __shared__ float mx[32];
    __shared__ int   bjs[32];
    __shared__ float pbuf[32 * 261];

    int bh = blockIdx.x;
    const float* A  = cv  + bh * 65536;   // A[i*256+j]
    const float* AT = cvT + bh * 65536;   // AT[j*256+i]
    int tid = threadIdx.x, lane = tid & 31, warp = tid >> 5;
    const float LMS = -6.2383246250395075f;  // log(1/512)
    const float LMB = -0.69314718055994531f; // log(1/2)
    const float L2W =  6.2383246250395075f;  // log(512)

    for (int k = tid; k < 257; k += 512) u[k] = 0.f;
    __syncthreads();

    for (int it = 0; it < 8; ++it) {
        // ========== v-step: lines are columns j; valid i in [j,255] ==========
        for (int base = 0; base < 257; base += 32) {
            #pragma unroll
            for (int q = 0; q < 2; ++q) {
                int li = 2 * warp + q;
                int l  = base + li;
                if (l <= 256) {
                    float pad = u[256];
                    float m = pad;
                    float t[8];
                    float* P = pbuf + li * 261;
                    if (l < 256) {
                        int k0 = l >> 5;               // chunks k<k0 fully masked
                        const float* R = AT + l * 256;
                        #pragma unroll
                        for (int k = 0; k < 8; ++k) {
                            if (k >= k0) {
                                int idx = lane + 32 * k;
                                t[k] = __fadd_rn(R[idx], u[idx]);
                                m = fmaxf(m, (idx >= l) ? t[k] : NEG_INF);
                            }
                        }
                        #pragma unroll
                        for (int off = 16; off; off >>= 1)
                            m = fmaxf(m, __shfl_xor_sync(0xffffffffu, m, off));
                        #pragma unroll
                        for (int k = 0; k < 8; ++k) {
                            int idx = lane + 32 * k;
                            float p = 0.f;
                            if (k >= k0 && idx >= l)
                                p = exp_acc(__fsub_rn(t[k], m));
                            P[idx] = p;
                        }
                    } else {
                        #pragma unroll
                        for (int k = 0; k < 8; ++k) {
                            int idx = lane + 32 * k;
                            t[k] = u[idx];
                            m = fmaxf(m, t[k]);
                        }
                        #pragma unroll
                        for (int off = 16; off; off >>= 1)
                            m = fmaxf(m, __shfl_xor_sync(0xffffffffu, m, off));
                        #pragma unroll
                        for (int k = 0; k < 8; ++k)
                            P[lane + 32 * k] = exp_acc(__fsub_rn(t[k], m));
                    }
                    if (lane == 0) mx[li] = m;
                }
            }
            __syncthreads();
            if (tid < 32) {
                int l = base + tid;
                if (l <= 256) {
                    const float* B = pbuf + tid * 261;
                    float m = mx[tid];
                    float s = 0.f;
                    #pragma unroll 8
                    for (int j = 0; j < 256; ++j) s = __fadd_rn(s, B[j]);
                    s = __fadd_rn(s, exp_acc(__fsub_rn(u[256], m)));   // pad LAST
                    v[l] = __fsub_rn((l < 256) ? LMS : LMB,
                                     __fadd_rn(m, log_acc(s)));
                }
            }
            __syncthreads();
        }
        // ========== u-step: lines are rows i; valid j in [0,i] ==========
        for (int base = 0; base < 257; base += 32) {
            #pragma unroll
            for (int q = 0; q < 2; ++q) {
                int li = 2 * warp + q;
                int l  = base + li;
                if (l <= 256) {
                    float pad = v[256];
                    float m = pad;
                    float t[8];
                    float* P = pbuf + li * 261;
                    if (l < 256) {
                        int k1 = l >> 5;               // chunks k>k1 fully masked
                        const float* R = A + l * 256;
                        #pragma unroll
                        for (int k = 0; k < 8; ++k) {
                            if (k <= k1) {
                                int idx = lane + 32 * k;
                                t[k] = __fadd_rn(R[idx], v[idx]);
                                m = fmaxf(m, (idx <= l) ? t[k] : NEG_INF);
                            }
                        }
                        #pragma unroll
                        for (int off = 16; off; off >>= 1)
                            m = fmaxf(m, __shfl_xor_sync(0xffffffffu, m, off));
                        #pragma unroll
                        for (int k = 0; k < 8; ++k) {
                            int idx = lane + 32 * k;
                            float p = 0.f;
                            if (k <= k1 && idx <= l)
                                p = exp_acc(__fsub_rn(t[k], m));
                            P[idx] = p;
                        }
                    } else {
                        #pragma unroll
                        for (int k = 0; k < 8; ++k) {
                            int idx = lane + 32 * k;
                            t[k] = v[idx];
                            m = fmaxf(m, t[k]);
                        }
                        #pragma unroll
                        for (int off = 16; off; off >>= 1)
                            m = fmaxf(m, __shfl_xor_sync(0xffffffffu, m, off));
                        #pragma unroll
                        for (int k = 0; k < 8; ++k)
                            P[lane + 32 * k] = exp_acc(__fsub_rn(t[k], m));
                    }
                    if (lane == 0) mx[li] = m;
                }
            }
            __syncthreads();
            if (tid < 32) {
                int l = base + tid;
                if (l <= 256) {
                    const float* B = pbuf + tid * 261;
                    float m = mx[tid];
                    float s = 0.f;
                    #pragma unroll 8
                    for (int j = 0; j < 256; ++j) s = __fadd_rn(s, B[j]);
                    s = __fadd_rn(s, exp_acc(__fsub_rn(v[256], m)));   // pad LAST
                    u[l] = __fsub_rn((l < 256) ? LMS : LMB,
                                     __fadd_rn(m, log_acc(s)));
                }
            }
            __syncthreads();
        }
    }

    // ====== Final: p = exp(((a+u)+v)+log512); argmax/occ/conf/corr ======
    for (int base = 0; base < 256; base += 32) {
        #pragma unroll
        for (int q = 0; q < 2; ++q) {
            int li = 2 * warp + q;
            int i  = base + li;                 // < 256 always
            int k1 = i >> 5;
            const float* R = A + i * 256;
            float ui = u[i];
            float* P = pbuf + li * 261;
            float bm = -1.f;
            int bj = 1 << 30;
            #pragma unroll
            for (int k = 0; k < 8; ++k) {
                int idx = lane + 32 * k;
                float p = 0.f;
                if (k <= k1 && idx <= i) {
                    float t = __fadd_rn(__fadd_rn(__fadd_rn(R[idx], ui), v[idx]), L2W);
                    p = exp_acc(t);
                    if (p > bm) { bm = p; bj = idx; }   // ascending idx within lane
                }
                P[idx] = p;
            }
            #pragma unroll
            for (int off = 16; off; off >>= 1) {
                float bm2 = __shfl_xor_sync(0xffffffffu, bm, off);
                int   bj2 = __shfl_xor_sync(0xffffffffu, bj, off);
                if (bm2 > bm || (bm2 == bm && bj2 < bj)) { bm = bm2; bj = bj2; }
            }
            if (lane == 0) bjs[li] = bj;
        }
        __syncthreads();
        if (tid < 32) {
            int i = base + tid;
            const float* B = pbuf + tid * 261;
            float sum = 0.f;
            #pragma unroll 8
            for (int j = 0; j < 256; ++j) sum = __fadd_rn(sum, B[j]);  // serial occ
            int bj = bjs[tid];
            float cf = 0.f, cn = 0.f;
            #pragma unroll
            for (int d = -2; d <= 2; ++d) {
                int jp = bj + d;
                if (jp >= 0 && jp < 256) {        // p is 0 beyond i already
                    float p = B[jp];
                    cf = __fadd_rn(cf, p);
                    cn = __fadd_rn(cn, __fmul_rn(p, (float)jp));
                }
            }
            float corr = __fdiv_rn(__fadd_rn(cn, 1e-4f), __fadd_rn(cf, 1e-4f));
            int o = bh * 256 + i;
            disp[o] = __fsub_rn((float)i, corr);
            conf[o] = cf;
            occ[o]  = sum;
        }
        __syncthreads();
    }
}

// ---------------------------------------------------------------------------
extern "C" void kernel_launch(void* const* d_in, const int* in_sizes, int n_in,
                              void* d_out, int out_size) {
    const float* feature = (const float*)d_in[0];
    const float* lnw     = (const float*)d_in[1];
    const float* lnb     = (const float*)d_in[2];
    float* out  = (float*)d_out;
    float* disp = out;
    float* conf = out + 81920;
    float* occ  = out + 163840;
    float* cv   = out + 245760;
    float* cvd  = out + 21217280;

    float* scratch;
    cudaGetSymbolAddress((void**)&scratch, g_scratch);

    ln_kernel<<<dim3(4, 80, 8), 256>>>(feature, lnw, lnb, scratch);
    gemm_kernel<<<dim3(4, 320), 256>>>(scratch, cv, cvd);
    transpose_kernel<<<dim3(64, 320), 256>>>(cv, scratch);
    sinkhorn_kernel<<<320, 512>>>(cv, scratch, disp, conf, occ);
}

// round 13
// speedup vs baseline: 1.2122x; 1.2122x over previous
#include <cuda_runtime.h>
#include <math.h>

// Shapes: feature (8,128,80,256) fp32; ln_weight/ln_bias (128)
// B2=4, H=80, W=256, C=128
// Outputs (concatenated fp32):
//   disparity (4,1,80,256)   @ 0          (81920)
//   conf      (4,1,80,256)   @ 81920      (81920)
//   occ       (4,1,80,256)   @ 163840     (81920)
//   cv        (4,80,256,256) @ 245760     (20971520)
//   cv_down   (4,40,128,128) @ 21217280   (2621440)

#define NEG_INF __int_as_float(0xff800000)

// 84 MB scratch: first holds xn, then reused as cvT.
__device__ float g_scratch[20971520];

// ---------------------------------------------------------------------------
// ~1-ulp fp32 exp/log from FFMA polynomials; deterministic, fast-math-immune.
// ---------------------------------------------------------------------------
__device__ __forceinline__ float exp_acc(float x) {
    if (x < -87.0f) return 0.f;
    float kf = rintf(x * 1.44269504088896341f);
    float f  = fmaf(kf, -6.93145752e-1f, x);
    f        = fmaf(kf, -1.42860677e-6f, f);
    float p = 1.98412698e-4f;
    p = fmaf(p, f, 1.38888889e-3f);
    p = fmaf(p, f, 8.33333333e-3f);
    p = fmaf(p, f, 4.16666667e-2f);
    p = fmaf(p, f, 1.66666667e-1f);
    p = fmaf(p, f, 5.0e-1f);
    p = fmaf(p, f, 1.0f);
    p = fmaf(p, f, 1.0f);
    int ki = (int)kf;
    return p * __int_as_float((ki + 127) << 23);
}

__device__ __forceinline__ float log_acc(float x) {
    int ix = __float_as_int(x);
    int e  = (ix >> 23) - 127;
    float mf = __int_as_float((ix & 0x7FFFFF) | 0x3F800000);
    if (mf > 1.41421356f) { mf *= 0.5f; e += 1; }
    float r  = (mf - 1.0f) / (mf + 1.0f);
    float r2 = r * r;
    float p = 0.10376f;
    p = fmaf(p, r2, 0.11119022f);
    p = fmaf(p, r2, 0.14285414f);
    p = fmaf(p, r2, 0.20000029f);
    p = fmaf(p, r2, 0.33333333f);
    p = fmaf(p, r2, 1.0f);
    p = 2.0f * r * p;
    float ef = (float)e;
    return fmaf(ef, 6.93145752e-1f, p) + ef * 1.42860677e-6f;
}

// ---------------------------------------------------------------------------
// Kernel 1: LayerNorm emulating XLA-CPU bit order (serial fp32 sums).
// feature[b,c,h,i] -> xn[((b*80+h)*256+i)*128+c]
// ---------------------------------------------------------------------------
__global__ void __launch_bounds__(256) ln_kernel(const float* __restrict__ f,
                                                 const float* __restrict__ lw,
                                                 const float* __restrict__ lb,
                                                 float* __restrict__ xn) {
    __shared__ float tile[128][65];
    __shared__ float mu[64], rs[64];
    __shared__ float wv[128], bv[128];
    int i0  = blockIdx.x * 64;
    int h   = blockIdx.y;
    int b   = blockIdx.z;
    int tid = threadIdx.x;
    if (tid < 128) { wv[tid] = lw[tid]; bv[tid] = lb[tid]; }

    const float* fp = f + ((b * 128) * 80 + h) * 256 + i0;
    for (int idx = tid; idx < 128 * 64; idx += 256) {
        int c = idx >> 6, ii = idx & 63;
        tile[c][ii] = fp[c * (80 * 256) + ii];
    }
    __syncthreads();

    if (tid < 64) {
        float s = 0.f;
        for (int c = 0; c < 128; ++c) s = __fadd_rn(s, tile[c][tid]);
        float muf = __fmul_rn(s, 0.0078125f);           // exact /128
        float vs = 0.f;
        for (int c = 0; c < 128; ++c) {
            float d = __fsub_rn(tile[c][tid], muf);
            vs = __fadd_rn(vs, __fmul_rn(d, d));
        }
        float varf = __fmul_rn(vs, 0.0078125f);
        mu[tid] = muf;
        rs[tid] = __fdiv_rn(1.0f, __fsqrt_rn(__fadd_rn(varf, 1e-5f)));
    }
    __syncthreads();

    float* op = xn + ((b * 80 + h) * 256 + i0) * 128;
    for (int idx = tid; idx < 8192; idx += 256) {
        int ii = idx >> 7, c = idx & 127;
        float xm = __fsub_rn(tile[c][ii], mu[ii]);
        float t  = __fmul_rn(__fmul_rn(xm, rs[ii]), wv[c]);
        op[ii * 128 + c] = __fadd_rn(t, bv[c]);
    }
}

// ---------------------------------------------------------------------------
// Kernel 2: cv = f0 @ f1^T per (b,h). Serial ascending-k FMA chain per output.
// Fused cv_down epilogue (even-h CTAs, bitwise-identical register values).
// ---------------------------------------------------------------------------
__global__ void __launch_bounds__(256) gemm_kernel(const float* __restrict__ xn,
                                                   float* __restrict__ cv,
                                                   float* __restrict__ cvd) {
    __shared__ float As[32][128];
    __shared__ float Bs[32][128];
    int bh = blockIdx.y;
    int ti = blockIdx.x >> 1, tj = blockIdx.x & 1;
    const float* Ag = xn + bh * 32768 + ti * 16384;
    const float* Bg = xn + (bh + 320) * 32768 + tj * 16384;
    int tid = threadIdx.x;
    int m0 = (tid >> 4) << 3;
    int n0 = (tid & 15) << 3;

    float acc[8][8];
    #pragma unroll
    for (int r = 0; r < 8; ++r)
        #pragma unroll
        for (int c = 0; c < 8; ++c) acc[r][c] = 0.f;

    for (int k0 = 0; k0 < 128; k0 += 32) {
        __syncthreads();
        #pragma unroll
        for (int q = tid; q < 1024; q += 256) {
            int m = q & 127, kq = q >> 7;
            float4 va = *(const float4*)(Ag + m * 128 + k0 + kq * 4);
            As[kq * 4 + 0][m] = va.x; As[kq * 4 + 1][m] = va.y;
            As[kq * 4 + 2][m] = va.z; As[kq * 4 + 3][m] = va.w;
            float4 vb = *(const float4*)(Bg + m * 128 + k0 + kq * 4);
            Bs[kq * 4 + 0][m] = vb.x; Bs[kq * 4 + 1][m] = vb.y;
            Bs[kq * 4 + 2][m] = vb.z; Bs[kq * 4 + 3][m] = vb.w;
        }
        __syncthreads();
        #pragma unroll 8
        for (int k = 0; k < 32; ++k) {
            float4 a0 = *(const float4*)&As[k][m0];
            float4 a1 = *(const float4*)&As[k][m0 + 4];
            float4 b0 = *(const float4*)&Bs[k][n0];
            float4 b1 = *(const float4*)&Bs[k][n0 + 4];
            float a[8] = {a0.x, a0.y, a0.z, a0.w, a1.x, a1.y, a1.z, a1.w};
            float bb[8] = {b0.x, b0.y, b0.z, b0.w, b1.x, b1.y, b1.z, b1.w};
            #pragma unroll
            for (int r = 0; r < 8; ++r)
                #pragma unroll
                for (int c = 0; c < 8; ++c) acc[r][c] = fmaf(a[r], bb[c], acc[r][c]);
        }
    }

    float* Cp = cv + bh * 65536 + (ti * 128 + m0) * 256 + tj * 128 + n0;
    #pragma unroll
    for (int r = 0; r < 8; ++r) {
        *(float4*)(Cp + r * 256)     = make_float4(acc[r][0], acc[r][1], acc[r][2], acc[r][3]);
        *(float4*)(Cp + r * 256 + 4) = make_float4(acc[r][4], acc[r][5], acc[r][6], acc[r][7]);
    }

    // Fused cv_down: cvd[b,hd,id,jd] = cv[b, 2hd, 2id, 2jd]
    int h = bh % 80;
    if (!(h & 1)) {
        int b  = bh / 80;
        int hd = h >> 1;
        float* Dp = cvd + ((b * 40 + hd) << 14);   // 128*128 per (b,hd)
        int jd0 = (tj * 128 + n0) >> 1;            // multiple of 4
        #pragma unroll
        for (int r = 0; r < 8; r += 2) {
            int id = (ti * 128 + m0 + r) >> 1;
            *(float4*)(Dp + id * 128 + jd0) =
                make_float4(acc[r][0], acc[r][2], acc[r][4], acc[r][6]);
        }
    }
}

// ---------------------------------------------------------------------------
// Kernel 3: per-(b,h) 256x256 transpose cv -> cvT
// ---------------------------------------------------------------------------
__global__ void __launch_bounds__(256) transpose_kernel(const float* __restrict__ cv,
                                                        float* __restrict__ cvT) {
    __shared__ float t[32][33];
    int bh = blockIdx.y;
    int ti = blockIdx.x >> 3, tj = blockIdx.x & 7;
    const float* src = cv + bh * 65536;
    float* dst = cvT + bh * 65536;
    int x = threadIdx.x & 31;
    int y = threadIdx.x >> 5;
    int i0 = ti * 32, j0 = tj * 32;
    #pragma unroll
    for (int r = y; r < 32; r += 8) t[r][x] = src[(i0 + r) * 256 + j0 + x];
    __syncthreads();
    #pragma unroll
    for (int r = y; r < 32; r += 8) dst[(j0 + r) * 256 + i0 + x] = t[x][r];
}

// ---------------------------------------------------------------------------
// Kernel 4: Sinkhorn + outputs. Arithmetic BIT-IDENTICAL to R11 (serial fp32
// chains, zero-filled masked slots, pad-last). New scheduling only:
// producer/consumer pipeline — warps 0-15 produce batch k's exp values into
// double-buffered pbuf while warp 16 consumes batch k-1's serial chains.
// One __syncthreads per step; chain latency hides behind production.
//
// Dynamic smem (floats): u[260] v[260] mx[2][32] bjs[2][32] pbuf[2][32*257]
// ---------------------------------------------------------------------------
#define SK_U     0
#define SK_V     260
#define SK_MX    520              // [2][32]
#define SK_BJ    584              // [2][32] (int)
#define SK_PB    648              // [2][32*257]
#define SK_FLOATS (648 + 2 * 32 * 257)
#define SK_BYTES  (SK_FLOATS * 4)

__global__ void __launch_bounds__(544, 2) sinkhorn_kernel(const float* __restrict__ cv,
                                                          const float* __restrict__ cvT,
                                                          float* __restrict__ disp,
                                                          float* __restrict__ conf,
                                                          float* __restrict__ occ) {
    extern __shared__ float sm[];
    float* u    = sm + SK_U;
    float* v    = sm + SK_V;
    float* mx   = sm + SK_MX;              // mx[bb*32 + li]
    int*   bjs  = (int*)(sm + SK_BJ);      // bjs[bb*32 + li]
    float* pbuf = sm + SK_PB;              // pbuf[bb*8224 + li*257 + j]

    int bh = blockIdx.x;
    const float* A  = cv  + bh * 65536;    // A[i*256+j]
    const float* AT = cvT + bh * 65536;    // AT[j*256+i]
    int tid  = threadIdx.x;
    int lane = tid & 31, warp = tid >> 5;  // warps 0-15 producers, 16 consumer
    const float LMS = -6.2383246250395075f;  // log(1/512)
    const float LMB = -0.69314718055994531f; // log(1/2)
    const float L2W =  6.2383246250395075f;  // log(512)

    for (int k = tid; k < 257; k += 544) u[k] = 0.f;
    __syncthreads();

    for (int it = 0; it < 8; ++it) {
        // ============ v-step: line l = column j; valid i in [l,255] ============
        for (int step = 0; step <= 9; ++step) {
            if (warp < 16) {
                if (step < 9) {
                    int li = warp * 2;
                    int bb = step & 1;
                    #pragma unroll
                    for (int q = 0; q < 2; ++q, ++li) {
                        int l = step * 32 + li;
                        if (l <= 256) {
                            float* P = pbuf + bb * 8224 + li * 257;
                            float pad = u[256];
                            float m = pad;
                            float t8[8];
                            if (l < 256) {
                                int k0 = l >> 5;
                                const float* R = AT + l * 256;
                                #pragma unroll
                                for (int k = 0; k < 8; ++k) {
                                    if (k >= k0) {
                                        int idx = lane + 32 * k;
                                        float t = __fadd_rn(R[idx], u[idx]);
                                        t8[k] = t;
                                        if (idx >= l) m = fmaxf(m, t);
                                    }
                                }
                                #pragma unroll
                                for (int off = 16; off; off >>= 1)
                                    m = fmaxf(m, __shfl_xor_sync(0xffffffffu, m, off));
                                #pragma unroll
                                for (int k = 0; k < 8; ++k) {
                                    int idx = lane + 32 * k;
                                    float p = 0.f;
                                    if (k >= k0 && idx >= l)
                                        p = exp_acc(__fsub_rn(t8[k], m));
                                    P[idx] = p;
                                }
                            } else {
                                #pragma unroll
                                for (int k = 0; k < 8; ++k) {
                                    float t = u[lane + 32 * k];
                                    t8[k] = t;
                                    m = fmaxf(m, t);
                                }
                                #pragma unroll
                                for (int off = 16; off; off >>= 1)
                                    m = fmaxf(m, __shfl_xor_sync(0xffffffffu, m, off));
                                #pragma unroll
                                for (int k = 0; k < 8; ++k)
                                    P[lane + 32 * k] = exp_acc(__fsub_rn(t8[k], m));
                            }
                            if (lane == 0) mx[bb * 32 + li] = m;
                        }
                    }
                }
            } else if (step >= 1) {
                int bIdx = step - 1;
                int bb = bIdx & 1;
                int l = bIdx * 32 + lane;
                if (l <= 256) {
                    const float* B = pbuf + bb * 8224 + lane * 257;
                    float m = mx[bb * 32 + lane];
                    float s = 0.f;
                    #pragma unroll 8
                    for (int j = 0; j < 256; ++j) s = __fadd_rn(s, B[j]);
                    s = __fadd_rn(s, exp_acc(__fsub_rn(u[256], m)));   // pad LAST
                    v[l] = __fsub_rn((l < 256) ? LMS : LMB,
                                     __fadd_rn(m, log_acc(s)));
                }
            }
            __syncthreads();
        }
        // ============ u-step: line l = row i; valid j in [0,l] ============
        for (int step = 0; step <= 9; ++step) {
            if (warp < 16) {
                if (step < 9) {
                    int li = warp * 2;
                    int bb = step & 1;
                    #pragma unroll
                    for (int q = 0; q < 2; ++q, ++li) {
                        int l = step * 32 + li;
                        if (l <= 256) {
                            float* P = pbuf + bb * 8224 + li * 257;
                            float pad = v[256];
                            float m = pad;
                            float t8[8];
                            if (l < 256) {
                                int k1 = l >> 5;
                                const float* R = A + l * 256;
                                #pragma unroll
                                for (int k = 0; k < 8; ++k) {
                                    if (k <= k1) {
                                        int idx = lane + 32 * k;
                                        float t = __fadd_rn(R[idx], v[idx]);
                                        t8[k] = t;
                                        if (idx <= l) m = fmaxf(m, t);
                                    }
                                }
                                #pragma unroll
                                for (int off = 16; off; off >>= 1)
                                    m = fmaxf(m, __shfl_xor_sync(0xffffffffu, m, off));
                                #pragma unroll
                                for (int k = 0; k < 8; ++k) {
                                    int idx = lane + 32 * k;
                                    float p = 0.f;
                                    if (k <= k1 && idx <= l)
                                        p = exp_acc(__fsub_rn(t8[k], m));
                                    P[idx] = p;
                                }
                            } else {
                                #pragma unroll
                                for (int k = 0; k < 8; ++k) {
                                    float t = v[lane + 32 * k];
                                    t8[k] = t;
                                    m = fmaxf(m, t);
                                }
                                #pragma unroll
                                for (int off = 16; off; off >>= 1)
                                    m = fmaxf(m, __shfl_xor_sync(0xffffffffu, m, off));
                                #pragma unroll
                                for (int k = 0; k < 8; ++k)
                                    P[lane + 32 * k] = exp_acc(__fsub_rn(t8[k], m));
                            }
                            if (lane == 0) mx[bb * 32 + li] = m;
                        }
                    }
                }
            } else if (step >= 1) {
                int bIdx = step - 1;
                int bb = bIdx & 1;
                int l = bIdx * 32 + lane;
                if (l <= 256) {
                    const float* B = pbuf + bb * 8224 + lane * 257;
                    float m = mx[bb * 32 + lane];
                    float s = 0.f;
                    #pragma unroll 8
                    for (int j = 0; j < 256; ++j) s = __fadd_rn(s, B[j]);
                    s = __fadd_rn(s, exp_acc(__fsub_rn(v[256], m)));   // pad LAST
                    u[l] = __fsub_rn((l < 256) ? LMS : LMB,
                                     __fadd_rn(m, log_acc(s)));
                }
            }
            __syncthreads();
        }
    }

    // ====== Final: p = exp(((a+u)+v)+log512); argmax/occ/conf/corr ======
    for (int step = 0; step <= 8; ++step) {
        if (warp < 16) {
            if (step < 8) {
                int li = warp * 2;
                int bb = step & 1;
                #pragma unroll
                for (int q = 0; q < 2; ++q, ++li) {
                    int i  = step * 32 + li;            // < 256 always
                    int k1 = i >> 5;
                    const float* R = A + i * 256;
                    float ui = u[i];
                    float* P = pbuf + bb * 8224 + li * 257;
                    float bm = -1.f;
                    int bj = 1 << 30;
                    #pragma unroll
                    for (int k = 0; k < 8; ++k) {
                        int idx = lane + 32 * k;
                        float p = 0.f;
                        if (k <= k1 && idx <= i) {
                            float t = __fadd_rn(__fadd_rn(__fadd_rn(R[idx], ui), v[idx]), L2W);
                            p = exp_acc(t);
                            if (p > bm) { bm = p; bj = idx; }   // ascending within lane
                        }
                        P[idx] = p;
                    }
                    #pragma unroll
                    for (int off = 16; off; off >>= 1) {
                        float bm2 = __shfl_xor_sync(0xffffffffu, bm, off);
                        int   bj2 = __shfl_xor_sync(0xffffffffu, bj, off);
                        if (bm2 > bm || (bm2 == bm && bj2 < bj)) { bm = bm2; bj = bj2; }
                    }
                    if (lane == 0) bjs[bb * 32 + li] = bj;
                }
            }
        } else if (step >= 1) {
            int bIdx = step - 1;
            int bb = bIdx & 1;
            int i = bIdx * 32 + lane;                   // < 256
            const float* B = pbuf + bb * 8224 + lane * 257;
            float sum = 0.f;
            #pragma unroll 8
            for (int j = 0; j < 256; ++j) sum = __fadd_rn(sum, B[j]);  // serial occ
            int bj = bjs[bb * 32 + lane];
            float cf = 0.f, cn = 0.f;
            #pragma unroll
            for (int d = -2; d <= 2; ++d) {
                int jp = bj + d;
                if (jp >= 0 && jp < 256) {              // zeros beyond i already
                    float p = B[jp];
                    cf = __fadd_rn(cf, p);
                    cn = __fadd_rn(cn, __fmul_rn(p, (float)jp));
                }
            }
            float corr = __fdiv_rn(__fadd_rn(cn, 1e-4f), __fadd_rn(cf, 1e-4f));
            int o = bh * 256 + i;
            disp[o] = __fsub_rn((float)i, corr);
            conf[o] = cf;
            occ[o]  = sum;
        }
        __syncthreads();
    }
}

// ---------------------------------------------------------------------------
extern "C" void kernel_launch(void* const* d_in, const int* in_sizes, int n_in,
                              void* d_out, int out_size) {
    const float* feature = (const float*)d_in[0];
    const float* lnw     = (const float*)d_in[1];
    const float* lnb     = (const float*)d_in[2];
    float* out  = (float*)d_out;
    float* disp = out;
    float* conf = out + 81920;
    float* occ  = out + 163840;
    float* cv   = out + 245760;
    float* cvd  = out + 21217280;

    float* scratch;
    cudaGetSymbolAddress((void**)&scratch, g_scratch);

    cudaFuncSetAttribute(sinkhorn_kernel,
                         cudaFuncAttributeMaxDynamicSharedMemorySize, SK_BYTES);

    ln_kernel<<<dim3(4, 80, 8), 256>>>(feature, lnw, lnb, scratch);
    gemm_kernel<<<dim3(4, 320), 256>>>(scratch, cv, cvd);
    transpose_kernel<<<dim3(64, 320), 256>>>(cv, scratch);
    sinkhorn_kernel<<<320, 544, SK_BYTES>>>(cv, scratch, disp, conf, occ);
}